// round 10
// baseline (speedup 1.0000x reference)
#include <cuda_runtime.h>
#include <cuda_bf16.h>
#include <cstdint>

// EdgeConvE: B=4, V=1024, C=64, E=16, K=32, OUT=128, NODES=4096, EDGES=131072
// src = repeat(arange(4096), 32) (structural) => segment n = edges [n*32,(n+1)*32)
// dst & 1023 = local neighbor (block-diagonal graphs).
//
// Algebra: feat@W = x_s@(W1-W2) + x_d@W2 + e@W3
//   A[n] = x_n@(W1-W2)+b ; C[n] = x_n@W2
//   out[n][j] = max(0, A[n][j] + max_k( C[dst_k][j] + (e_k . W3[:,j]) ))
// e@W3 via mma.sync.m16n8k8 tf32 (3xTF32). Gathers via cp.async.bulk (TMA
// path) -> no L1tex lane-scatter wavefronts.

#define NODES 4096
#define VDIM  1024
#define CDIM  64
#define EDIM  16
#define KNBR  32
#define OUTD  128
#define ENPB  2
#define EPAD  20     // E smem row stride (floats): 20 mod 32 -> conflict-free
#define CPAD  136    // C smem row stride (floats): 136 mod 32 = 8 -> 2-wf floor

__device__ float g_A[NODES * OUTD];
__device__ float g_C[NODES * OUTD];

// ---------------- helpers ----------------
__device__ __forceinline__ uint64_t pack_f32x2(float lo, float hi) {
    uint64_t r;
    asm("mov.b64 %0, {%1, %2};" : "=l"(r) : "f"(lo), "f"(hi));
    return r;
}
__device__ __forceinline__ void unpack_f32x2(float& lo, float& hi, uint64_t v) {
    asm("mov.b64 {%0, %1}, %2;" : "=f"(lo), "=f"(hi) : "l"(v));
}
__device__ __forceinline__ uint64_t fma_f32x2(uint64_t a, uint64_t b, uint64_t c) {
    uint64_t d;
    asm("fma.rn.f32x2 %0, %1, %2, %3;" : "=l"(d) : "l"(a), "l"(b), "l"(c));
    return d;
}
__device__ __forceinline__ uint64_t lds_u64(uint32_t addr) {
    uint64_t a;
    asm("ld.shared.u64 %0, [%1];" : "=l"(a) : "r"(addr));
    return a;
}
__device__ __forceinline__ uint32_t smem_u32(const void* p) {
    return (uint32_t)__cvta_generic_to_shared(p);
}
__device__ __forceinline__ uint32_t f2tf32(float f) {
    uint32_t u;
    asm("cvt.rna.tf32.f32 %0, %1;" : "=r"(u) : "f"(f));
    return u;
}
__device__ __forceinline__ void mma_tf32(float* c, const uint32_t* a, const uint32_t* b) {
    asm volatile(
        "mma.sync.aligned.m16n8k8.row.col.f32.tf32.tf32.f32 "
        "{%0,%1,%2,%3}, {%4,%5,%6,%7}, {%8,%9}, {%0,%1,%2,%3};"
        : "+f"(c[0]), "+f"(c[1]), "+f"(c[2]), "+f"(c[3])
        : "r"(a[0]), "r"(a[1]), "r"(a[2]), "r"(a[3]), "r"(b[0]), "r"(b[1]));
}
__device__ __forceinline__ void bulk_g2s(uint32_t s, const void* g, int bytes, uint32_t mb) {
    asm volatile(
        "cp.async.bulk.shared::cta.global.mbarrier::complete_tx::bytes "
        "[%0], [%1], %2, [%3];"
        :: "r"(s), "l"(g), "r"(bytes), "r"(mb) : "memory");
}
__device__ __forceinline__ void mbar_init(uint32_t mb, uint32_t cnt) {
    asm volatile("mbarrier.init.shared.b64 [%0], %1;" :: "r"(mb), "r"(cnt) : "memory");
}
__device__ __forceinline__ void mbar_expect_tx(uint32_t mb, uint32_t bytes) {
    asm volatile("mbarrier.arrive.expect_tx.shared.b64 _, [%0], %1;"
                 :: "r"(mb), "r"(bytes) : "memory");
}
__device__ __forceinline__ void mbar_wait(uint32_t mb, uint32_t parity) {
    asm volatile(
        "{\n\t.reg .pred P;\n\t"
        "WAIT_%=:\n\t"
        "mbarrier.try_wait.parity.acquire.cta.shared::cta.b64 P, [%0], %1, 0x989680;\n\t"
        "@!P bra.uni WAIT_%=;\n\t}"
        :: "r"(mb), "r"(parity) : "memory");
}

// ---------------------------------------------------------------------------
// Kernel 1: per-node linear tables (f32x2-packed over node pairs). grid 1024.
// ---------------------------------------------------------------------------
#define NT_NODES 4
__global__ void __launch_bounds__(128) node_tables_kernel(
    const float* __restrict__ x, const float* __restrict__ W,
    const float* __restrict__ bias)
{
    __shared__ float xs[CDIM][NT_NODES];
    const int j  = threadIdx.x;
    const int n0 = blockIdx.x * NT_NODES;

    for (int it = 0; it < NT_NODES * CDIM / 128; it++) {
        int idx = j + it * 128;
        xs[idx & 63][idx >> 6] = x[n0 * CDIM + idx];
    }
    __syncthreads();

    const float bj = bias[j];
    uint64_t accA[NT_NODES / 2], accC[NT_NODES / 2];
#pragma unroll
    for (int p = 0; p < NT_NODES / 2; p++) {
        accA[p] = pack_f32x2(bj, bj);
        accC[p] = pack_f32x2(0.0f, 0.0f);
    }
    const uint32_t xs_base = smem_u32(&xs[0][0]);

#pragma unroll 8
    for (int c = 0; c < CDIM; c++) {
        const float w1 = W[c * OUTD + j];
        const float w2 = W[(CDIM + c) * OUTD + j];
        const uint64_t wd2 = pack_f32x2(w1 - w2, w1 - w2);
        const uint64_t w22 = pack_f32x2(w2, w2);
        const uint32_t rowa = xs_base + c * (NT_NODES * 4);
#pragma unroll
        for (int p = 0; p < NT_NODES / 2; p++) {
            uint64_t xv2 = lds_u64(rowa + p * 8);
            accA[p] = fma_f32x2(xv2, wd2, accA[p]);
            accC[p] = fma_f32x2(xv2, w22, accC[p]);
        }
    }
#pragma unroll
    for (int p = 0; p < NT_NODES / 2; p++) {
        float a0, a1, c0, c1;
        unpack_f32x2(a0, a1, accA[p]);
        unpack_f32x2(c0, c1, accC[p]);
        g_A[(n0 + 2 * p) * OUTD + j]     = a0;
        g_A[(n0 + 2 * p + 1) * OUTD + j] = a1;
        g_C[(n0 + 2 * p) * OUTD + j]     = c0;
        g_C[(n0 + 2 * p + 1) * OUTD + j] = c1;
    }
}

// ---------------------------------------------------------------------------
// Kernel 2: TMA-bulk-gather tensor-core edge kernel. 2 nodes/block, grid 2048.
//   Warp p (p<2) issues node p's 32 E-row (64B) + 32 C-row (512B) bulks,
//   completion tracked by mbarrier expect_tx. Compute identical to R8 but
//   C comes from smem (bank-tuned) instead of scattered LDGs.
// ---------------------------------------------------------------------------
__global__ void __launch_bounds__(128) edge_max_kernel(
    const float* __restrict__ eattr,  // [4,1024,1024,16]
    const float* __restrict__ W,      // [144,128]
    const int*   __restrict__ dst,    // [131072]
    float*       __restrict__ out)    // [4096,128]
{
    const int t  = threadIdx.x;
    const int w  = t >> 5;
    const int l  = t & 31;
    const int g  = l >> 2;
    const int c4 = l & 3;
    const int node0 = blockIdx.x * ENPB;

    __shared__ int sd[ENPB][KNBR];
    __shared__ __align__(16) float sE[ENPB][KNBR][EPAD];
    __shared__ __align__(16) float sC[ENPB][KNBR][CPAD];
    __shared__ __align__(8)  uint64_t mbar[ENPB];

    if (t < ENPB) mbar_init(smem_u32(&mbar[t]), 1);
    if (t < ENPB * KNBR) sd[t >> 5][t & 31] = dst[node0 * KNBR + t];
    __syncthreads();
    asm volatile("fence.proxy.async.shared::cta;" ::: "memory");

    // ---- issue phase: warp p gathers node p's rows via bulk copies ----
    if (w < ENPB) {
        const uint32_t mb = smem_u32(&mbar[w]);
        if (l == 0) mbar_expect_tx(mb, KNBR * (64 + 512));
        const int dk = sd[w][l];
        const float* es = eattr + ((size_t)(node0 + w) * VDIM + (dk & (VDIM - 1))) * EDIM;
        bulk_g2s(smem_u32(&sE[w][l][0]), es, 64, mb);
        const float* cs = g_C + (size_t)dk * OUTD;
        bulk_g2s(smem_u32(&sC[w][l][0]), cs, 512, mb);
    }

    // ---- overlap: B-frags (W3, hi/lo tf32 split) + A rows ----
    uint32_t bhi[4][2][2], blo[4][2][2];
#pragma unroll
    for (int nt = 0; nt < 4; nt++) {
#pragma unroll
        for (int kt = 0; kt < 2; kt++) {
            const int col = 32 * w + 8 * nt + g;
            const float b0 = W[(2 * CDIM + 8 * kt + c4) * OUTD + col];
            const float b1 = W[(2 * CDIM + 8 * kt + c4 + 4) * OUTD + col];
            bhi[nt][kt][0] = f2tf32(b0);
            blo[nt][kt][0] = f2tf32(b0 - __uint_as_float(bhi[nt][kt][0]));
            bhi[nt][kt][1] = f2tf32(b1);
            blo[nt][kt][1] = f2tf32(b1 - __uint_as_float(bhi[nt][kt][1]));
        }
    }

#pragma unroll
    for (int p = 0; p < ENPB; p++) {
        const int n = node0 + p;
        mbar_wait(smem_u32(&mbar[p]), 0);

        float cm0[4], cm1[4];
#pragma unroll
        for (int nt = 0; nt < 4; nt++) { cm0[nt] = -1e30f; cm1[nt] = -1e30f; }

#pragma unroll
        for (int mt = 0; mt < 2; mt++) {
            const int r0 = 16 * mt + g;
            const int r1 = r0 + 8;

            // A-frags from sE (conflict-free), 3xTF32 split
            uint32_t ahi[2][4], alo[2][4];
#pragma unroll
            for (int kt = 0; kt < 2; kt++) {
                float af[4];
                af[0] = sE[p][r0][8 * kt + c4];
                af[1] = sE[p][r1][8 * kt + c4];
                af[2] = sE[p][r0][8 * kt + c4 + 4];
                af[3] = sE[p][r1][8 * kt + c4 + 4];
#pragma unroll
                for (int i = 0; i < 4; i++) {
                    ahi[kt][i] = f2tf32(af[i]);
                    alo[kt][i] = f2tf32(af[i] - __uint_as_float(ahi[kt][i]));
                }
            }

#pragma unroll
            for (int nt = 0; nt < 4; nt++) {
                float acc[4] = {0.0f, 0.0f, 0.0f, 0.0f};
#pragma unroll
                for (int kt = 0; kt < 2; kt++) {
                    mma_tf32(acc, ahi[kt], bhi[nt][kt]);
                    mma_tf32(acc, alo[kt], bhi[nt][kt]);
                    mma_tf32(acc, ahi[kt], blo[nt][kt]);
                }
                const int jc = 32 * w + 8 * nt + 2 * c4;
                const float2 cv0 = *reinterpret_cast<const float2*>(&sC[p][r0][jc]);
                const float2 cv1 = *reinterpret_cast<const float2*>(&sC[p][r1][jc]);
                cm0[nt] = fmaxf(cm0[nt], fmaxf(acc[0] + cv0.x, acc[2] + cv1.x));
                cm1[nt] = fmaxf(cm1[nt], fmaxf(acc[1] + cv0.y, acc[3] + cv1.y));
            }
        }

        // max over 8 lane-groups, add A, relu, store
#pragma unroll
        for (int nt = 0; nt < 4; nt++) {
            float v0 = cm0[nt], v1 = cm1[nt];
#pragma unroll
            for (int off = 4; off <= 16; off <<= 1) {
                v0 = fmaxf(v0, __shfl_xor_sync(0xffffffffu, v0, off));
                v1 = fmaxf(v1, __shfl_xor_sync(0xffffffffu, v1, off));
            }
            if (l < 4) {
                const int j0 = 32 * w + 8 * nt + 2 * l;
                const float2 av = *reinterpret_cast<const float2*>(g_A + n * OUTD + j0);
                float2 r;
                r.x = fmaxf(v0 + av.x, 0.0f);
                r.y = fmaxf(v1 + av.y, 0.0f);
                *reinterpret_cast<float2*>(out + n * OUTD + j0) = r;
            }
        }
    }
}

// ---------------------------------------------------------------------------
// Inputs: 0 node_features [4,1024,64] f32 | 1 edge_attributes [4,1024,1024,16] f32
//         2 W [144,128] f32 | 3 b [128] f32 | 4 src i32 (unused) | 5 dst i32
// Output: f32 [4,1024,128]
// ---------------------------------------------------------------------------
extern "C" void kernel_launch(void* const* d_in, const int* in_sizes, int n_in,
                              void* d_out, int out_size)
{
    const float* x     = (const float*)d_in[0];
    const float* eattr = (const float*)d_in[1];
    const float* W     = (const float*)d_in[2];
    const float* bias  = (const float*)d_in[3];
    const int*   dst   = (const int*)d_in[5];
    float*       out   = (float*)d_out;

    node_tables_kernel<<<NODES / NT_NODES, 128>>>(x, W, bias);
    edge_max_kernel<<<NODES / ENPB, 128>>>(eattr, W, dst, out);
}